// round 5
// baseline (speedup 1.0000x reference)
#include <cuda_runtime.h>
#include <cstdint>

#define FULL_MASK 0xFFFFFFFFu
#define NQ 8
#define DEPTH 3
#define FDIM 512
#define NCLS 10

// Deferred-CNOT masks (GF(2)); layout p = (lane<<3)|r, r = qubit bits 0..2.
// parity table for 3-bit values: 0x96
// s_c[g][bL]: {oA.x,oA.y,pA.x,pA.y} and {oB.x,oB.y,pB.x,pB.y}  (g = gate-8)
template<int PM, int W>
__device__ __forceinline__ void gate_apply(float ar[8], float ai[8],
                                           const float4* __restrict__ sc, int lane)
{
    constexpr int pr = PM & 7;
    constexpr int pl = PM >> 3;
    constexpr int wr = W & 7;
    constexpr int wl = W >> 3;

    int bL = 0;
    if constexpr (wl != 0) bL = __popc(lane & wl) & 1;
    float4 CA = sc[bL * 2 + 0];
    float4 CB = sc[bL * 2 + 1];
    const float2 oA = make_float2(CA.x, CA.y), pA = make_float2(CA.z, CA.w);
    const float2 oB = make_float2(CB.x, CB.y), pB = make_float2(CB.z, CB.w);

    if constexpr (pl == 0) {
        #pragma unroll
        for (int r = 0; r < 8; r++) {
            if (((0x96 >> (r & wr)) & 1) == 0) {   // base of pair (compile-time)
                const int r1 = r ^ pr;
                float a0r = ar[r],  a0i = ai[r];
                float a1r = ar[r1], a1i = ai[r1];
                ar[r]  = oA.x*a0r - oA.y*a0i + pA.x*a1r - pA.y*a1i;
                ai[r]  = oA.x*a0i + oA.y*a0r + pA.x*a1i + pA.y*a1r;
                ar[r1] = oB.x*a1r - oB.y*a1i + pB.x*a0r - pB.y*a0i;
                ai[r1] = oB.x*a1i + oB.y*a1r + pB.x*a0i + pB.y*a0r;
            }
        }
    } else if constexpr (pr == 0) {
        #pragma unroll
        for (int r = 0; r < 8; r++) {
            float tr = __shfl_xor_sync(FULL_MASK, ar[r], pl);
            float ti = __shfl_xor_sync(FULL_MASK, ai[r], pl);
            const bool pb = ((0x96 >> (r & wr)) & 1) != 0;   // compile-time
            float2 o = pb ? oB : oA;
            float2 p = pb ? pB : pA;
            float nr = o.x*ar[r] - o.y*ai[r] + p.x*tr - p.y*ti;
            float ni = o.x*ai[r] + o.y*ar[r] + p.x*ti + p.y*tr;
            ar[r] = nr; ai[r] = ni;
        }
    } else {
        #pragma unroll
        for (int r = 0; r < 8; r++) {
            if (r < (r ^ pr)) {                       // compile-time pair rep
                const int r1 = r ^ pr;
                float sr0 = __shfl_xor_sync(FULL_MASK, ar[r1], pl);
                float si0 = __shfl_xor_sync(FULL_MASK, ai[r1], pl);
                float sr1 = __shfl_xor_sync(FULL_MASK, ar[r],  pl);
                float si1 = __shfl_xor_sync(FULL_MASK, ai[r],  pl);
                const bool pb0 = ((0x96 >> (r  & wr)) & 1) != 0;
                const bool pb1 = ((0x96 >> (r1 & wr)) & 1) != 0;
                float2 o0 = pb0 ? oB : oA, p0 = pb0 ? pB : pA;
                float2 o1 = pb1 ? oB : oA, p1 = pb1 ? pB : pA;
                float nr0 = o0.x*ar[r]  - o0.y*ai[r]  + p0.x*sr0 - p0.y*si0;
                float ni0 = o0.x*ai[r]  + o0.y*ar[r]  + p0.x*si0 + p0.y*sr0;
                float nr1 = o1.x*ar[r1] - o1.y*ai[r1] + p1.x*sr1 - p1.y*si1;
                float ni1 = o1.x*ai[r1] + o1.y*ar[r1] + p1.x*si1 + p1.y*sr1;
                ar[r]  = nr0; ai[r]  = ni0;
                ar[r1] = nr1; ai[r1] = ni1;
            }
        }
    }
}

__global__ void __launch_bounds__(256, 4) qiskit_head_kernel(
    const float* __restrict__ x,       // (B, 512)
    const float* __restrict__ proj_w,  // (8, 512)
    const float* __restrict__ qnn_w,   // (72,)
    const float* __restrict__ out_w,   // (10, 8)
    const float* __restrict__ out_b,   // (10,)
    float* __restrict__ out,           // (B, 10)
    int B)
{
    __shared__ __align__(16) float s_pw[NQ * FDIM];   // 16 KB
    __shared__ float4 s_g4[NQ][2];                    // layer-0 gates (raw form)
    __shared__ float4 s_c[2 * NQ * DEPTH - 2 * NQ][2][2]; // gates 8..23, parity-indexed
    __shared__ float  s_ow[NCLS * NQ];
    __shared__ float  s_ob[NCLS];

    const int tid  = threadIdx.x;
    const int lane = tid & 31;
    const int warp = tid >> 5;

    #pragma unroll 4
    for (int i = tid; i < NQ * FDIM; i += 256) s_pw[i] = proj_w[i];
    if (tid < NCLS * NQ) s_ow[tid] = out_w[tid];
    if (tid < NCLS)      s_ob[tid] = out_b[tid];
    if (tid < DEPTH * NQ) {
        float w0 = qnn_w[tid * 3 + 0];
        float w1 = qnn_w[tid * 3 + 1];
        float w2 = qnn_w[tid * 3 + 2];
        float c0, s0, c1, s1, c2, s2;
        sincosf(0.5f * w0, &s0, &c0);
        sincosf(0.5f * w1, &s1, &c1);
        sincosf(0.5f * w2, &s2, &c2);
        float2 A00 = { c1 * c0,  s1 * s0};
        float2 A01 = {-s1 * c0, -c1 * s0};
        float2 A10 = { s1 * c0, -c1 * s0};
        float2 A11 = { c1 * c0, -s1 * s0};
        float2 g00 = make_float2(c2 * A00.x + s2 * A10.y, c2 * A00.y - s2 * A10.x);
        float2 g01 = make_float2(c2 * A01.x + s2 * A11.y, c2 * A01.y - s2 * A11.x);
        float2 g10 = make_float2(c2 * A10.x + s2 * A00.y, c2 * A10.y - s2 * A00.x);
        float2 g11 = make_float2(c2 * A11.x + s2 * A01.y, c2 * A11.y - s2 * A01.x);
        if (tid < NQ) {
            s_g4[tid][0] = make_float4(g00.x, g00.y, g01.x, g01.y);
            s_g4[tid][1] = make_float4(g10.x, g10.y, g11.x, g11.y);
        } else {
            const int g = tid - NQ;
            // parity 0: oA=u00 pA=u01 | oB=u11 pB=u10
            s_c[g][0][0] = make_float4(g00.x, g00.y, g01.x, g01.y);
            s_c[g][0][1] = make_float4(g11.x, g11.y, g10.x, g10.y);
            // parity 1: oA=u11 pA=u10 | oB=u00 pB=u01
            s_c[g][1][0] = make_float4(g11.x, g11.y, g10.x, g10.y);
            s_c[g][1][1] = make_float4(g00.x, g00.y, g01.x, g01.y);
        }
    }
    __syncthreads();

    auto mrg = [&](float a, float b, int dist) {
        float c = (lane & dist) ? b : a;
        float d = (lane & dist) ? a : b;
        return c + __shfl_xor_sync(FULL_MASK, d, dist);
    };
    auto srcLane = [](int q) { return ((q & 1) << 4) | (((q >> 1) & 1) << 3) | (((q >> 2) & 1) << 2); };

    const int gw      = blockIdx.x * 8 + warp;   // global warp id
    const int wstride = gridDim.x * 8;           // 4736

    for (int b = gw; b < B; b += wstride) {

        // ---- projection: acc[q] = x[b] . proj_w[q] ----
        float acc[NQ];
        #pragma unroll
        for (int q = 0; q < NQ; q++) acc[q] = 0.f;
        const float4* xr = (const float4*)(x + (size_t)b * FDIM);
        #pragma unroll
        for (int ch = 0; ch < 4; ch++) {
            float4 xv = xr[ch * 32 + lane];
            #pragma unroll
            for (int q = 0; q < NQ; q++) {
                float4 wv = *(const float4*)&s_pw[q * FDIM + ch * 128 + lane * 4];
                acc[q] += xv.x*wv.x + xv.y*wv.y + xv.z*wv.z + xv.w*wv.w;
            }
        }
        {
            float m0 = mrg(acc[0], acc[1], 16), m1 = mrg(acc[2], acc[3], 16);
            float m2 = mrg(acc[4], acc[5], 16), m3 = mrg(acc[6], acc[7], 16);
            float n0 = mrg(m0, m1, 8), n1 = mrg(m2, m3, 8);
            float f  = mrg(n0, n1, 4);
            f += __shfl_xor_sync(FULL_MASK, f, 2);
            f += __shfl_xor_sync(FULL_MASK, f, 1);
            acc[0] = f;
        }
        float cv, sv;
        {
            float h = tanhf(acc[0]) * 0.78539816339744830962f;
            __sincosf(h, &sv, &cv);
        }
        float cq[NQ], sq[NQ];
        #pragma unroll
        for (int q = 0; q < NQ; q++) {
            cq[q] = __shfl_sync(FULL_MASK, cv, srcLane(q));
            sq[q] = __shfl_sync(FULL_MASK, sv, srcLane(q));
        }

        // ---- state after encoding + layer-0 gates: product state ----
        float Lr = 1.f, Li = 0.f;
        #pragma unroll
        for (int k = 0; k < 5; k++) {
            const int q = k + 3;
            const int bit = (lane >> k) & 1;
            float4 V = s_g4[q][bit];                 // indexed LDS.128
            float wx = V.x * cq[q] + V.z * sq[q];
            float wy = V.y * cq[q] + V.w * sq[q];
            float nr = Lr*wx - Li*wy;
            float ni = Lr*wy + Li*wx;
            Lr = nr; Li = ni;
        }
        float ar[8], ai[8];
        {
            float4 A0 = s_g4[0][0], B0 = s_g4[0][1];
            float a0x = A0.x*cq[0] + A0.z*sq[0], a0y = A0.y*cq[0] + A0.w*sq[0];
            float b0x = B0.x*cq[0] + B0.z*sq[0], b0y = B0.y*cq[0] + B0.w*sq[0];
            ar[0] = Lr*a0x - Li*a0y;  ai[0] = Lr*a0y + Li*a0x;
            ar[1] = Lr*b0x - Li*b0y;  ai[1] = Lr*b0y + Li*b0x;

            float4 A1 = s_g4[1][0], B1 = s_g4[1][1];
            float a1x = A1.x*cq[1] + A1.z*sq[1], a1y = A1.y*cq[1] + A1.w*sq[1];
            float b1x = B1.x*cq[1] + B1.z*sq[1], b1y = B1.y*cq[1] + B1.w*sq[1];
            #pragma unroll
            for (int r = 0; r < 2; r++) {
                float tr = ar[r], ti = ai[r];
                ar[r + 2] = tr*b1x - ti*b1y;  ai[r + 2] = tr*b1y + ti*b1x;
                ar[r]     = tr*a1x - ti*a1y;  ai[r]     = tr*a1y + ti*a1x;
            }

            float4 A2 = s_g4[2][0], B2 = s_g4[2][1];
            float a2x = A2.x*cq[2] + A2.z*sq[2], a2y = A2.y*cq[2] + A2.w*sq[2];
            float b2x = B2.x*cq[2] + B2.z*sq[2], b2y = B2.y*cq[2] + B2.w*sq[2];
            #pragma unroll
            for (int r = 0; r < 4; r++) {
                float tr = ar[r], ti = ai[r];
                ar[r + 4] = tr*b2x - ti*b2y;  ai[r + 4] = tr*b2y + ti*b2x;
                ar[r]     = tr*a2x - ti*a2y;  ai[r]     = tr*a2y + ti*a2x;
            }
        }

        // ---- layers 1,2 with deferred-CNOT masks ----
        #define GATE(idx, PMv, Wv) gate_apply<PMv, Wv>(ar, ai, &s_c[(idx) - 8][0][0], lane)
        // layer 1 (phi = C)
        GATE(8,  0x03, 0xFE); GATE(9,  0x06, 0x03); GATE(10, 0x0C, 0x07); GATE(11, 0x18, 0x0F);
        GATE(12, 0x30, 0x1F); GATE(13, 0x60, 0x3F); GATE(14, 0xC0, 0x7F); GATE(15, 0x83, 0xFF);
        // layer 2 (phi = C^2)
        GATE(16, 0x05, 0xAB); GATE(17, 0x0A, 0xFD); GATE(18, 0x14, 0xFA); GATE(19, 0x28, 0xF5);
        GATE(20, 0x50, 0xEA); GATE(21, 0xA0, 0xD5); GATE(22, 0x43, 0xAA); GATE(23, 0x86, 0x55);
        #undef GATE

        // ---- PauliZ via Walsh-Hadamard of |amp|^2 (phi = C^3) ----
        float S[8];
        #pragma unroll
        for (int r = 0; r < 8; r++) S[r] = ar[r]*ar[r] + ai[r]*ai[r];
        #pragma unroll
        for (int st = 0; st < 3; st++) {
            const int d = 1 << st;
            #pragma unroll
            for (int r = 0; r < 8; r++) {
                if (!(r & d)) {
                    float a = S[r] + S[r + d];
                    float bm = S[r] - S[r + d];
                    S[r] = a; S[r + d] = bm;
                }
            }
        }
        auto sg = [&](int wl, float v) { return (__popc(lane & wl) & 1) ? -v : v; };
        float z0 = sg(0x06, S[2]), z1 = sg(0x0A, S[6]);
        float z2 = sg(0x15, S[4]), z3 = sg(0x0B, S[1]);
        float z4 = sg(0x16, S[3]), z5 = sg(0x0C, S[6]);
        float z6 = sg(0x19, S[4]), z7 = sg(0x13, S[1]);
        float m0 = mrg(z0, z1, 16), m1 = mrg(z2, z3, 16);
        float m2 = mrg(z4, z5, 16), m3 = mrg(z6, z7, 16);
        float n0 = mrg(m0, m1, 8),  n1 = mrg(m2, m3, 8);
        float f  = mrg(n0, n1, 4);
        f += __shfl_xor_sync(FULL_MASK, f, 2);
        f += __shfl_xor_sync(FULL_MASK, f, 1);
        float g[NQ];
        #pragma unroll
        for (int q = 0; q < NQ; q++) g[q] = __shfl_sync(FULL_MASK, f, srcLane(q));

        // ---- output head ----
        if (lane < NCLS) {
            float o = s_ob[lane];
            #pragma unroll
            for (int q = 0; q < NQ; q++) o += g[q] * s_ow[lane * NQ + q];
            out[(size_t)b * NCLS + lane] = o;
        }
    }
}

extern "C" void kernel_launch(void* const* d_in, const int* in_sizes, int n_in,
                              void* d_out, int out_size) {
    const float* x      = (const float*)d_in[0];
    const float* proj_w = (const float*)d_in[1];
    const float* qnn_w  = (const float*)d_in[2];
    const float* out_w  = (const float*)d_in[3];
    const float* out_b  = (const float*)d_in[4];
    float* out = (float*)d_out;

    int B = in_sizes[0] / FDIM;   // 8192
    int blocks = 592;             // 148 SMs x 4 blocks: exact single wave
    qiskit_head_kernel<<<blocks, 256>>>(x, proj_w, qnn_w, out_w, out_b, out, B);
}